// round 8
// baseline (speedup 1.0000x reference)
#include <cuda_runtime.h>
#include <cstdint>

#define N_NODES 100000
#define IN_CH   512
#define HID     16
#define OUT_CH  64
#define MAX_E   3200000
#define NBLK    ((N_NODES + 255) / 256)   // scan blocks

typedef unsigned long long u64;

// ---------------- device scratch (static, no allocation) ----------------
__device__ float g_dinv[N_NODES];
__device__ int   g_cnt[N_NODES];
__device__ int   g_pre[N_NODES];
__device__ int   g_bsum[NBLK];
__device__ int   g_boff[NBLK];
__device__ int   g_rowptr[N_NODES + 1];
__device__ int   g_cur[N_NODES];
__device__ int2  g_csr[MAX_E];            // (src, w-bits) per edge, bucketed by dst
__device__ float g_h1[N_NODES * HID];     // layer1 linear out
__device__ float g_hr[N_NODES * HID];     // relu'd hidden after layer1 conv

// ---------------- f32x2 helpers ----------------
__device__ __forceinline__ u64 pack2(float lo, float hi) {
    u64 r; asm("mov.b64 %0, {%1, %2};" : "=l"(r) : "f"(lo), "f"(hi)); return r;
}
__device__ __forceinline__ u64 fma2(u64 a, u64 b, u64 c) {
    u64 d; asm("fma.rn.f32x2 %0, %1, %2, %3;" : "=l"(d) : "l"(a), "l"(b), "l"(c)); return d;
}
__device__ __forceinline__ float2 unpack2(u64 v) {
    float2 f; asm("mov.b64 {%0, %1}, %2;" : "=f"(f.x), "=f"(f.y) : "l"(v)); return f;
}

// ---------------- GEMM1: h1 = x @ W1, k-pair-packed f32x2 ----------------
// Tile: 512 rows x 16 cols. 256 threads: thread = 8 rows (stride 64) x 4 cols.
// x staged ROW-MAJOR in smem (pitch 20 floats -> conflict-free strided reads).
// Accumulators pack (even-k, odd-k) partial sums; halves summed at the end.
#define XS_PITCH 20
__global__ void __launch_bounds__(256, 2) k_gemm1(const float* __restrict__ x,
                                                  const float* __restrict__ W, int n) {
    __shared__ __align__(16) float xs[512 * XS_PITCH];  // 40 KB
    __shared__ __align__(16) u64   wp[8 * HID];         // k-pairs x 16 cols, 1 KB

    const int t = threadIdx.x;
    const int rowBase = blockIdx.x * 512;
    const int rg = t >> 2;   // 0..63
    const int jg = t & 3;    // col group (4 cols)

    u64 acc[8][4];
#pragma unroll
    for (int r = 0; r < 8; r++)
#pragma unroll
        for (int j = 0; j < 4; j++) acc[r][j] = 0ull;

    for (int kk = 0; kk < IN_CH; kk += 16) {
        // stage W k-pairs: wp[kp][j] = (W[kk+2kp][j], W[kk+2kp+1][j])
        if (t < 128) {
            int kp = t >> 4, j = t & 15;
            wp[kp * HID + j] = pack2(W[(kk + 2 * kp) * HID + j],
                                     W[(kk + 2 * kp + 1) * HID + j]);
        }
        // stage x rows (row-major, 4 lanes per row -> 8 lines per warp-instr)
#pragma unroll
        for (int p = 0; p < 8; p++) {
            int row = (t >> 2) + p * 64;
            int ko = (t & 3) * 4;
            int grow = rowBase + row;
            float4 v = make_float4(0.f, 0.f, 0.f, 0.f);
            if (grow < n)
                v = *reinterpret_cast<const float4*>(&x[(size_t)grow * IN_CH + kk + ko]);
            *reinterpret_cast<float4*>(&xs[row * XS_PITCH + ko]) = v;
        }
        __syncthreads();
#pragma unroll
        for (int k4 = 0; k4 < 4; k4++) {
            // W pairs for this k-quad: kp0 = 2*k4, kp1 = 2*k4+1
            u64 w0[4], w1[4];
            *reinterpret_cast<ulonglong2*>(&w0[0]) =
                *reinterpret_cast<const ulonglong2*>(&wp[(2 * k4) * HID + jg * 4]);
            *reinterpret_cast<ulonglong2*>(&w0[2]) =
                *reinterpret_cast<const ulonglong2*>(&wp[(2 * k4) * HID + jg * 4 + 2]);
            *reinterpret_cast<ulonglong2*>(&w1[0]) =
                *reinterpret_cast<const ulonglong2*>(&wp[(2 * k4 + 1) * HID + jg * 4]);
            *reinterpret_cast<ulonglong2*>(&w1[2]) =
                *reinterpret_cast<const ulonglong2*>(&wp[(2 * k4 + 1) * HID + jg * 4 + 2]);
#pragma unroll
            for (int r = 0; r < 8; r++) {
                ulonglong2 xq = *reinterpret_cast<const ulonglong2*>(
                    &xs[(rg + 64 * r) * XS_PITCH + k4 * 4]);
#pragma unroll
                for (int j = 0; j < 4; j++) {
                    acc[r][j] = fma2(xq.x, w0[j], acc[r][j]);
                    acc[r][j] = fma2(xq.y, w1[j], acc[r][j]);
                }
            }
        }
        __syncthreads();
    }
    // epilogue: sum the (even,odd) halves, store float4
#pragma unroll
    for (int r = 0; r < 8; r++) {
        int grow = rowBase + rg + 64 * r;
        if (grow < n) {
            float2 a0 = unpack2(acc[r][0]);
            float2 a1 = unpack2(acc[r][1]);
            float2 a2 = unpack2(acc[r][2]);
            float2 a3 = unpack2(acc[r][3]);
            reinterpret_cast<float4*>(&g_h1[(size_t)grow * HID])[jg] =
                make_float4(a0.x + a0.y, a1.x + a1.y, a2.x + a2.y, a3.x + a3.y);
        }
    }
}

// ---------------- CSR build ----------------
__global__ void k_zero_cnt(int n) {
    int i = blockIdx.x * blockDim.x + threadIdx.x;
    if (i < n) g_cnt[i] = 0;
}

__global__ void k_hist(const int* __restrict__ dst, int e) {
    int i = blockIdx.x * blockDim.x + threadIdx.x;
    if (i < e) atomicAdd(&g_cnt[dst[i]], 1);
}

__global__ void __launch_bounds__(256) k_scanA(int n) {
    __shared__ int s[256];
    int t = threadIdx.x;
    int i = blockIdx.x * 256 + t;
    int v = (i < n) ? g_cnt[i] : 0;
    s[t] = v;
    __syncthreads();
#pragma unroll
    for (int off = 1; off < 256; off <<= 1) {
        int add = (t >= off) ? s[t - off] : 0;
        __syncthreads();
        s[t] += add;
        __syncthreads();
    }
    if (i < n) g_pre[i] = s[t] - v;               // exclusive
    if (t == 255) g_bsum[blockIdx.x] = s[255];
}

__global__ void __launch_bounds__(512) k_scanB(int nb) {
    __shared__ int s[512];
    int t = threadIdx.x;
    int v = (t < nb) ? g_bsum[t] : 0;
    s[t] = v;
    __syncthreads();
#pragma unroll
    for (int off = 1; off < 512; off <<= 1) {
        int add = (t >= off) ? s[t - off] : 0;
        __syncthreads();
        s[t] += add;
        __syncthreads();
    }
    if (t < nb) g_boff[t] = s[t] - v;             // exclusive
}

__global__ void k_scanC(int n) {
    int i = blockIdx.x * blockDim.x + threadIdx.x;
    if (i >= n) return;
    int rp = g_pre[i] + g_boff[i >> 8];
    g_rowptr[i] = rp;
    g_cur[i] = rp;
    g_dinv[i] = rsqrtf((float)g_cnt[i] + 1.0f);   // +1 self loop
    if (i == n - 1) g_rowptr[n] = rp + g_cnt[i];
}

__global__ void k_scatter(const int* __restrict__ src,
                          const int* __restrict__ dst, int e) {
    int i = blockIdx.x * blockDim.x + threadIdx.x;
    if (i >= e) return;
    int s = src[i];
    int d = dst[i];
    float w = g_dinv[s] * g_dinv[d];
    int pos = atomicAdd(&g_cur[d], 1);
    g_csr[pos] = make_int2(s, __float_as_int(w));
}

// ---------------- gather layer 1 (fused self-loop + bias + relu) ----------------
__global__ void __launch_bounds__(256) k_gather1(const float* __restrict__ b1, int n) {
    int wid = (blockIdx.x * 256 + threadIdx.x) >> 5;
    if (wid >= n) return;
    int lane = threadIdx.x & 31;
    int ql = lane & 7, qh = lane >> 3;
    int row = g_rowptr[wid], end = g_rowptr[wid + 1];

    float2 acc = make_float2(0.f, 0.f);
    for (int i = row + qh; i < end; i += 4) {
        int2 ec = g_csr[i];
        float w = __int_as_float(ec.y);
        float2 hv = *reinterpret_cast<const float2*>(&g_h1[(size_t)ec.x * HID + ql * 2]);
        acc.x += w * hv.x;
        acc.y += w * hv.y;
    }
    acc.x += __shfl_xor_sync(0xffffffffu, acc.x, 8);
    acc.y += __shfl_xor_sync(0xffffffffu, acc.y, 8);
    acc.x += __shfl_xor_sync(0xffffffffu, acc.x, 16);
    acc.y += __shfl_xor_sync(0xffffffffu, acc.y, 16);

    float di = g_dinv[wid];
    float sl = di * di;
    float2 hv = *reinterpret_cast<const float2*>(&g_h1[(size_t)wid * HID + ql * 2]);
    float2 bb = *reinterpret_cast<const float2*>(&b1[ql * 2]);
    float2 r;
    r.x = fmaxf(acc.x + hv.x * sl + bb.x, 0.f);
    r.y = fmaxf(acc.y + hv.y * sl + bb.y, 0.f);
    if (qh == 0)
        *reinterpret_cast<float2*>(&g_hr[(size_t)wid * HID + ql * 2]) = r;
}

// ---------------- gather layer 2 (fused W2 GEMM + log-softmax) ----------------
__global__ void __launch_bounds__(256) k_gather2(const float* __restrict__ W2,
                                                 const float* __restrict__ b2,
                                                 float* __restrict__ out, int n) {
    __shared__ float W2s[HID * OUT_CH];  // 4 KB
    for (int i = threadIdx.x; i < HID * OUT_CH; i += 256) W2s[i] = W2[i];
    __syncthreads();

    int wid = (blockIdx.x * 256 + threadIdx.x) >> 5;
    if (wid >= n) return;
    int lane = threadIdx.x & 31;
    int ql = lane & 7, qh = lane >> 3;
    int row = g_rowptr[wid], end = g_rowptr[wid + 1];

    float2 acc = make_float2(0.f, 0.f);
    for (int i = row + qh; i < end; i += 4) {
        int2 ec = g_csr[i];
        float w = __int_as_float(ec.y);
        float2 hv = *reinterpret_cast<const float2*>(&g_hr[(size_t)ec.x * HID + ql * 2]);
        acc.x += w * hv.x;
        acc.y += w * hv.y;
    }
    acc.x += __shfl_xor_sync(0xffffffffu, acc.x, 8);
    acc.y += __shfl_xor_sync(0xffffffffu, acc.y, 8);
    acc.x += __shfl_xor_sync(0xffffffffu, acc.x, 16);
    acc.y += __shfl_xor_sync(0xffffffffu, acc.y, 16);

    float di = g_dinv[wid];
    float sl = di * di;
    float2 hv = *reinterpret_cast<const float2*>(&g_hr[(size_t)wid * HID + ql * 2]);
    float tx = acc.x + hv.x * sl;   // t[2*ql] (lanes 0..7 hold the 16-dim vector)
    float ty = acc.y + hv.y * sl;   // t[2*ql+1]

    float y0 = b2[lane];
    float y1 = b2[lane + 32];
#pragma unroll
    for (int k = 0; k < 8; k++) {
        float a = __shfl_sync(0xffffffffu, tx, k);
        float b = __shfl_sync(0xffffffffu, ty, k);
        y0 += a * W2s[(2 * k) * OUT_CH + lane]      + b * W2s[(2 * k + 1) * OUT_CH + lane];
        y1 += a * W2s[(2 * k) * OUT_CH + lane + 32] + b * W2s[(2 * k + 1) * OUT_CH + lane + 32];
    }
    float m = fmaxf(y0, y1);
#pragma unroll
    for (int o = 16; o; o >>= 1) m = fmaxf(m, __shfl_xor_sync(0xffffffffu, m, o));
    float se = expf(y0 - m) + expf(y1 - m);
#pragma unroll
    for (int o = 16; o; o >>= 1) se += __shfl_xor_sync(0xffffffffu, se, o);
    float lg = m + logf(se);
    out[(size_t)wid * OUT_CH + lane]      = y0 - lg;
    out[(size_t)wid * OUT_CH + lane + 32] = y1 - lg;
}

// ---------------- launch ----------------
extern "C" void kernel_launch(void* const* d_in, const int* in_sizes, int n_in,
                              void* d_out, int out_size) {
    const float* x    = (const float*)d_in[0];
    const int*   ei   = (const int*)d_in[1];     // int32 (JAX x64 disabled)
    const float* W1   = (const float*)d_in[2];
    const float* b1   = (const float*)d_in[3];
    const float* W2   = (const float*)d_in[4];
    const float* b2   = (const float*)d_in[5];
    float* out        = (float*)d_out;

    const int n = in_sizes[0] / IN_CH;       // 100000
    const int e = in_sizes[1] / 2;           // 3200000
    const int* src = ei;
    const int* dst = ei + e;

    const int TB = 256;
    int gb_n = (n + TB - 1) / TB;            // == NBLK
    int gb_e = (e + TB - 1) / TB;
    int gb_w = (n * 32 + TB - 1) / TB;       // warp-per-node kernels
    int gb_g = (n + 511) / 512;              // gemm tiles

    // gemm1 kept as launch #4 — ncu profiles the 4th launch.
    k_zero_cnt<<<gb_n, TB>>>(n);             // 1
    k_hist<<<gb_e, TB>>>(dst, e);            // 2
    k_scanA<<<gb_n, TB>>>(n);                // 3
    k_gemm1<<<gb_g, 256>>>(x, W1, n);        // 4  <-- profiled
    k_scanB<<<1, 512>>>(gb_n);               // 5
    k_scanC<<<gb_n, TB>>>(n);                // 6
    k_scatter<<<gb_e, TB>>>(src, dst, e);    // 7
    k_gather1<<<gb_w, TB>>>(b1, n);          // 8
    k_gather2<<<gb_w, TB>>>(W2, b2, out, n); // 9
}

// round 9
// speedup vs baseline: 1.5986x; 1.5986x over previous
#include <cuda_runtime.h>
#include <cstdint>

#define N_NODES 100000
#define IN_CH   512
#define HID     16
#define OUT_CH  64
#define MAX_E   3200000
#define NBLK    ((N_NODES + 255) / 256)   // scan blocks

typedef unsigned long long u64;

// ---------------- device scratch (static, no allocation) ----------------
__device__ float g_dinv[N_NODES];
__device__ int   g_cnt[N_NODES];
__device__ int   g_pre[N_NODES];
__device__ int   g_bsum[NBLK];
__device__ int   g_boff[NBLK];
__device__ int   g_rowptr[N_NODES + 1];
__device__ int   g_cur[N_NODES];
__device__ int2  g_csr[MAX_E];            // (src, w-bits) per edge, bucketed by dst
__device__ float g_h1[N_NODES * HID];     // layer1 linear out
__device__ float g_hr[N_NODES * HID];     // relu'd hidden after layer1 conv

// ---------------- f32x2 helpers ----------------
__device__ __forceinline__ u64 pack2(float lo, float hi) {
    u64 r; asm("mov.b64 %0, {%1, %2};" : "=l"(r) : "f"(lo), "f"(hi)); return r;
}
__device__ __forceinline__ u64 fma2(u64 a, u64 b, u64 c) {
    u64 d; asm("fma.rn.f32x2 %0, %1, %2, %3;" : "=l"(d) : "l"(a), "l"(b), "l"(c)); return d;
}
__device__ __forceinline__ float2 unpack2(u64 v) {
    float2 f; asm("mov.b64 {%0, %1}, %2;" : "=f"(f.x), "=f"(f.y) : "l"(v)); return f;
}

// ---------------- GEMM1: h1 = x @ W1, k-pair f32x2, 256-row tile ----------------
// 256 threads: thread = 4 rows (stride 64) x 4 cols. acc[4][4] u64 = 32 regs.
// x staged ROW-MAJOR (STS.128 only), pitch 20 floats -> conflict-free reads.
#define XS_PITCH 20
__global__ void __launch_bounds__(256, 3) k_gemm1(const float* __restrict__ x,
                                                  const float* __restrict__ W, int n) {
    __shared__ __align__(16) float xs[256 * XS_PITCH];  // 20 KB
    __shared__ __align__(16) u64   wp[8 * HID];         // 8 k-pairs x 16 cols, 1 KB

    const int t = threadIdx.x;
    const int rowBase = blockIdx.x * 256;
    const int rg = t >> 2;   // 0..63
    const int jg = t & 3;    // col group (4 cols)
    const int ko = (t & 3) * 4;

    u64 acc[4][4];
#pragma unroll
    for (int r = 0; r < 4; r++)
#pragma unroll
        for (int j = 0; j < 4; j++) acc[r][j] = 0ull;

    for (int kk = 0; kk < IN_CH; kk += 16) {
        // stage W k-pairs: wp[kp][j] = (W[kk+2kp][j], W[kk+2kp+1][j])
        if (t < 128) {
            int kp = t >> 4, j = t & 15;
            wp[kp * HID + j] = pack2(W[(kk + 2 * kp) * HID + j],
                                     W[(kk + 2 * kp + 1) * HID + j]);
        }
        // stage 256 rows x 16 k, row-major: 4 passes of LDG.128 + STS.128
#pragma unroll
        for (int p = 0; p < 4; p++) {
            int row = (t >> 2) + p * 64;
            int grow = rowBase + row;
            float4 v = make_float4(0.f, 0.f, 0.f, 0.f);
            if (grow < n)
                v = *reinterpret_cast<const float4*>(&x[(size_t)grow * IN_CH + kk + ko]);
            *reinterpret_cast<float4*>(&xs[row * XS_PITCH + ko]) = v;
        }
        __syncthreads();
#pragma unroll
        for (int k4 = 0; k4 < 4; k4++) {
            u64 w0[4], w1[4];
            *reinterpret_cast<ulonglong2*>(&w0[0]) =
                *reinterpret_cast<const ulonglong2*>(&wp[(2 * k4) * HID + jg * 4]);
            *reinterpret_cast<ulonglong2*>(&w0[2]) =
                *reinterpret_cast<const ulonglong2*>(&wp[(2 * k4) * HID + jg * 4 + 2]);
            *reinterpret_cast<ulonglong2*>(&w1[0]) =
                *reinterpret_cast<const ulonglong2*>(&wp[(2 * k4 + 1) * HID + jg * 4]);
            *reinterpret_cast<ulonglong2*>(&w1[2]) =
                *reinterpret_cast<const ulonglong2*>(&wp[(2 * k4 + 1) * HID + jg * 4 + 2]);
#pragma unroll
            for (int r = 0; r < 4; r++) {
                ulonglong2 xq = *reinterpret_cast<const ulonglong2*>(
                    &xs[(rg + 64 * r) * XS_PITCH + k4 * 4]);
#pragma unroll
                for (int j = 0; j < 4; j++) {
                    acc[r][j] = fma2(xq.x, w0[j], acc[r][j]);
                    acc[r][j] = fma2(xq.y, w1[j], acc[r][j]);
                }
            }
        }
        __syncthreads();
    }
    // epilogue: sum (even,odd) halves, store float4
#pragma unroll
    for (int r = 0; r < 4; r++) {
        int grow = rowBase + rg + 64 * r;
        if (grow < n) {
            float2 a0 = unpack2(acc[r][0]);
            float2 a1 = unpack2(acc[r][1]);
            float2 a2 = unpack2(acc[r][2]);
            float2 a3 = unpack2(acc[r][3]);
            reinterpret_cast<float4*>(&g_h1[(size_t)grow * HID])[jg] =
                make_float4(a0.x + a0.y, a1.x + a1.y, a2.x + a2.y, a3.x + a3.y);
        }
    }
}

// ---------------- CSR build ----------------
__global__ void k_zero_cnt(int n) {
    int i = blockIdx.x * blockDim.x + threadIdx.x;
    if (i < n) g_cnt[i] = 0;
}

__global__ void k_hist(const int* __restrict__ dst, int e) {
    int i = blockIdx.x * blockDim.x + threadIdx.x;
    if (i < e) atomicAdd(&g_cnt[dst[i]], 1);
}

__global__ void __launch_bounds__(256) k_scanA(int n) {
    __shared__ int s[256];
    int t = threadIdx.x;
    int i = blockIdx.x * 256 + t;
    int v = (i < n) ? g_cnt[i] : 0;
    s[t] = v;
    __syncthreads();
#pragma unroll
    for (int off = 1; off < 256; off <<= 1) {
        int add = (t >= off) ? s[t - off] : 0;
        __syncthreads();
        s[t] += add;
        __syncthreads();
    }
    if (i < n) g_pre[i] = s[t] - v;               // exclusive
    if (t == 255) g_bsum[blockIdx.x] = s[255];
}

__global__ void __launch_bounds__(512) k_scanB(int nb) {
    __shared__ int s[512];
    int t = threadIdx.x;
    int v = (t < nb) ? g_bsum[t] : 0;
    s[t] = v;
    __syncthreads();
#pragma unroll
    for (int off = 1; off < 512; off <<= 1) {
        int add = (t >= off) ? s[t - off] : 0;
        __syncthreads();
        s[t] += add;
        __syncthreads();
    }
    if (t < nb) g_boff[t] = s[t] - v;             // exclusive
}

__global__ void k_scanC(int n) {
    int i = blockIdx.x * blockDim.x + threadIdx.x;
    if (i >= n) return;
    int rp = g_pre[i] + g_boff[i >> 8];
    g_rowptr[i] = rp;
    g_cur[i] = rp;
    g_dinv[i] = rsqrtf((float)g_cnt[i] + 1.0f);   // +1 self loop
    if (i == n - 1) g_rowptr[n] = rp + g_cnt[i];
}

__global__ void k_scatter(const int* __restrict__ src,
                          const int* __restrict__ dst, int e) {
    int i = blockIdx.x * blockDim.x + threadIdx.x;
    if (i >= e) return;
    int s = src[i];
    int d = dst[i];
    float w = g_dinv[s] * g_dinv[d];
    int pos = atomicAdd(&g_cur[d], 1);
    g_csr[pos] = make_int2(s, __float_as_int(w));
}

// ---------------- gather layer 1 (fused self-loop + bias + relu) ----------------
__global__ void __launch_bounds__(256) k_gather1(const float* __restrict__ b1, int n) {
    int wid = (blockIdx.x * 256 + threadIdx.x) >> 5;
    if (wid >= n) return;
    int lane = threadIdx.x & 31;
    int ql = lane & 7, qh = lane >> 3;
    int row = g_rowptr[wid], end = g_rowptr[wid + 1];

    float2 acc = make_float2(0.f, 0.f);
    for (int i = row + qh; i < end; i += 4) {
        int2 ec = g_csr[i];
        float w = __int_as_float(ec.y);
        float2 hv = *reinterpret_cast<const float2*>(&g_h1[(size_t)ec.x * HID + ql * 2]);
        acc.x += w * hv.x;
        acc.y += w * hv.y;
    }
    acc.x += __shfl_xor_sync(0xffffffffu, acc.x, 8);
    acc.y += __shfl_xor_sync(0xffffffffu, acc.y, 8);
    acc.x += __shfl_xor_sync(0xffffffffu, acc.x, 16);
    acc.y += __shfl_xor_sync(0xffffffffu, acc.y, 16);

    float di = g_dinv[wid];
    float sl = di * di;
    float2 hv = *reinterpret_cast<const float2*>(&g_h1[(size_t)wid * HID + ql * 2]);
    float2 bb = *reinterpret_cast<const float2*>(&b1[ql * 2]);
    float2 r;
    r.x = fmaxf(acc.x + hv.x * sl + bb.x, 0.f);
    r.y = fmaxf(acc.y + hv.y * sl + bb.y, 0.f);
    if (qh == 0)
        *reinterpret_cast<float2*>(&g_hr[(size_t)wid * HID + ql * 2]) = r;
}

// ---------------- gather layer 2 (fused W2 GEMM + log-softmax) ----------------
__global__ void __launch_bounds__(256) k_gather2(const float* __restrict__ W2,
                                                 const float* __restrict__ b2,
                                                 float* __restrict__ out, int n) {
    __shared__ float W2s[HID * OUT_CH];  // 4 KB
    for (int i = threadIdx.x; i < HID * OUT_CH; i += 256) W2s[i] = W2[i];
    __syncthreads();

    int wid = (blockIdx.x * 256 + threadIdx.x) >> 5;
    if (wid >= n) return;
    int lane = threadIdx.x & 31;
    int ql = lane & 7, qh = lane >> 3;
    int row = g_rowptr[wid], end = g_rowptr[wid + 1];

    float2 acc = make_float2(0.f, 0.f);
    for (int i = row + qh; i < end; i += 4) {
        int2 ec = g_csr[i];
        float w = __int_as_float(ec.y);
        float2 hv = *reinterpret_cast<const float2*>(&g_hr[(size_t)ec.x * HID + ql * 2]);
        acc.x += w * hv.x;
        acc.y += w * hv.y;
    }
    acc.x += __shfl_xor_sync(0xffffffffu, acc.x, 8);
    acc.y += __shfl_xor_sync(0xffffffffu, acc.y, 8);
    acc.x += __shfl_xor_sync(0xffffffffu, acc.x, 16);
    acc.y += __shfl_xor_sync(0xffffffffu, acc.y, 16);

    float di = g_dinv[wid];
    float sl = di * di;
    float2 hv = *reinterpret_cast<const float2*>(&g_hr[(size_t)wid * HID + ql * 2]);
    float tx = acc.x + hv.x * sl;   // t[2*ql] (lanes 0..7 hold the 16-dim vector)
    float ty = acc.y + hv.y * sl;   // t[2*ql+1]

    float y0 = b2[lane];
    float y1 = b2[lane + 32];
#pragma unroll
    for (int k = 0; k < 8; k++) {
        float a = __shfl_sync(0xffffffffu, tx, k);
        float b = __shfl_sync(0xffffffffu, ty, k);
        y0 += a * W2s[(2 * k) * OUT_CH + lane]      + b * W2s[(2 * k + 1) * OUT_CH + lane];
        y1 += a * W2s[(2 * k) * OUT_CH + lane + 32] + b * W2s[(2 * k + 1) * OUT_CH + lane + 32];
    }
    float m = fmaxf(y0, y1);
#pragma unroll
    for (int o = 16; o; o >>= 1) m = fmaxf(m, __shfl_xor_sync(0xffffffffu, m, o));
    float se = expf(y0 - m) + expf(y1 - m);
#pragma unroll
    for (int o = 16; o; o >>= 1) se += __shfl_xor_sync(0xffffffffu, se, o);
    float lg = m + logf(se);
    out[(size_t)wid * OUT_CH + lane]      = y0 - lg;
    out[(size_t)wid * OUT_CH + lane + 32] = y1 - lg;
}

// ---------------- launch ----------------
extern "C" void kernel_launch(void* const* d_in, const int* in_sizes, int n_in,
                              void* d_out, int out_size) {
    const float* x    = (const float*)d_in[0];
    const int*   ei   = (const int*)d_in[1];     // int32 (JAX x64 disabled)
    const float* W1   = (const float*)d_in[2];
    const float* b1   = (const float*)d_in[3];
    const float* W2   = (const float*)d_in[4];
    const float* b2   = (const float*)d_in[5];
    float* out        = (float*)d_out;

    const int n = in_sizes[0] / IN_CH;       // 100000
    const int e = in_sizes[1] / 2;           // 3200000
    const int* src = ei;
    const int* dst = ei + e;

    const int TB = 256;
    int gb_n = (n + TB - 1) / TB;            // == NBLK
    int gb_e = (e + TB - 1) / TB;
    int gb_w = (n * 32 + TB - 1) / TB;       // warp-per-node kernels

    // gemm1 kept as launch #4 — ncu profiles the 4th launch.
    k_zero_cnt<<<gb_n, TB>>>(n);             // 1
    k_hist<<<gb_e, TB>>>(dst, e);            // 2
    k_scanA<<<gb_n, TB>>>(n);                // 3
    k_gemm1<<<gb_n, 256>>>(x, W1, n);        // 4  <-- profiled
    k_scanB<<<1, 512>>>(gb_n);               // 5
    k_scanC<<<gb_n, TB>>>(n);                // 6
    k_scatter<<<gb_e, TB>>>(src, dst, e);    // 7
    k_gather1<<<gb_w, TB>>>(b1, n);          // 8
    k_gather2<<<gb_w, TB>>>(W2, b2, out, n); // 9
}

// round 10
// speedup vs baseline: 1.6716x; 1.0457x over previous
#include <cuda_runtime.h>
#include <cstdint>

#define N_NODES 100000
#define IN_CH   512
#define HID     16
#define OUT_CH  64
#define MAX_E   3200000
#define NBLK    ((N_NODES + 255) / 256)   // scan blocks

typedef unsigned long long u64;

// ---------------- device scratch (static, no allocation) ----------------
__device__ float g_dinv[N_NODES];
__device__ int   g_cnt[N_NODES];
__device__ int   g_pre[N_NODES];
__device__ int   g_bsum[NBLK];
__device__ int   g_boff[NBLK];
__device__ int   g_rowptr[N_NODES + 1];
__device__ int   g_cur[N_NODES];
__device__ int2  g_csr[MAX_E];            // (src, w-bits) per edge, bucketed by dst
__device__ float g_h1[N_NODES * HID];     // layer1 linear out
__device__ float g_hr[N_NODES * HID];     // relu'd hidden after layer1 conv

// ---------------- f32x2 / cp.async helpers ----------------
__device__ __forceinline__ u64 pack2(float lo, float hi) {
    u64 r; asm("mov.b64 %0, {%1, %2};" : "=l"(r) : "f"(lo), "f"(hi)); return r;
}
__device__ __forceinline__ u64 fma2(u64 a, u64 b, u64 c) {
    u64 d; asm("fma.rn.f32x2 %0, %1, %2, %3;" : "=l"(d) : "l"(a), "l"(b), "l"(c)); return d;
}
__device__ __forceinline__ float2 unpack2(u64 v) {
    float2 f; asm("mov.b64 {%0, %1}, %2;" : "=f"(f.x), "=f"(f.y) : "l"(v)); return f;
}
__device__ __forceinline__ void cpasync16(uint32_t saddr, const void* g, int srcbytes) {
    asm volatile("cp.async.cg.shared.global [%0], [%1], 16, %2;"
                 :: "r"(saddr), "l"(g), "r"(srcbytes));
}
__device__ __forceinline__ void cp_commit() {
    asm volatile("cp.async.commit_group;");
}
template <int N>
__device__ __forceinline__ void cp_wait() {
    asm volatile("cp.async.wait_group %0;" :: "n"(N));
}

// ---------------- GEMM1: h1 = x @ W1, k-pair f32x2, cp.async double-buffered ----------------
// 256 threads: thread = 4 rows (stride 64) x 4 cols. acc[4][4] u64 = 32 regs.
// x staged ROW-MAJOR via cp.async (16B), pitch 20 floats -> conflict-free reads.
#define XS_PITCH 20
#define NCHUNK   (IN_CH / 16)   // 32
__global__ void __launch_bounds__(256, 3) k_gemm1(const float* __restrict__ x,
                                                  const float* __restrict__ W, int n) {
    __shared__ __align__(16) float xs[2][256 * XS_PITCH];  // 2 x 20 KB
    __shared__ __align__(16) u64   wp[2][8 * HID];         // 2 x 1 KB

    const int t = threadIdx.x;
    const int rowBase = blockIdx.x * 256;
    const int rg = t >> 2;   // 0..63
    const int jg = t & 3;    // col group (4 cols)
    const int ko = (t & 3) * 4;

    // stage x chunk kk into buffer b (4 cp.async of 16B per thread)
    auto stage_x = [&](int kk, int b) {
#pragma unroll
        for (int p = 0; p < 4; p++) {
            int row = (t >> 2) + p * 64;
            int grow = rowBase + row;
            bool ok = (grow < n);
            const float* gp = ok ? &x[(size_t)grow * IN_CH + kk + ko] : x;
            uint32_t sa = (uint32_t)__cvta_generic_to_shared(&xs[b][row * XS_PITCH + ko]);
            cpasync16(sa, gp, ok ? 16 : 0);
        }
    };
    // stage W k-pairs for chunk kk into buffer b (plain STS; 1 KB)
    auto stage_w = [&](int kk, int b) {
        if (t < 128) {
            int kp = t >> 4, j = t & 15;
            wp[b][kp * HID + j] = pack2(W[(kk + 2 * kp) * HID + j],
                                        W[(kk + 2 * kp + 1) * HID + j]);
        }
    };

    u64 acc[4][4];
#pragma unroll
    for (int r = 0; r < 4; r++)
#pragma unroll
        for (int j = 0; j < 4; j++) acc[r][j] = 0ull;

    stage_x(0, 0);
    stage_w(0, 0);
    cp_commit();

    int buf = 0;
    for (int c = 0; c < NCHUNK; c++) {
        if (c < NCHUNK - 1) {
            stage_x((c + 1) * 16, buf ^ 1);
            stage_w((c + 1) * 16, buf ^ 1);
            cp_commit();
            cp_wait<1>();   // oldest group (current buf) complete
        } else {
            cp_wait<0>();
        }
        __syncthreads();

#pragma unroll
        for (int k4 = 0; k4 < 4; k4++) {
            u64 w0[4], w1[4];
            *reinterpret_cast<ulonglong2*>(&w0[0]) =
                *reinterpret_cast<const ulonglong2*>(&wp[buf][(2 * k4) * HID + jg * 4]);
            *reinterpret_cast<ulonglong2*>(&w0[2]) =
                *reinterpret_cast<const ulonglong2*>(&wp[buf][(2 * k4) * HID + jg * 4 + 2]);
            *reinterpret_cast<ulonglong2*>(&w1[0]) =
                *reinterpret_cast<const ulonglong2*>(&wp[buf][(2 * k4 + 1) * HID + jg * 4]);
            *reinterpret_cast<ulonglong2*>(&w1[2]) =
                *reinterpret_cast<const ulonglong2*>(&wp[buf][(2 * k4 + 1) * HID + jg * 4 + 2]);
#pragma unroll
            for (int r = 0; r < 4; r++) {
                ulonglong2 xq = *reinterpret_cast<const ulonglong2*>(
                    &xs[buf][(rg + 64 * r) * XS_PITCH + k4 * 4]);
#pragma unroll
                for (int j = 0; j < 4; j++) {
                    acc[r][j] = fma2(xq.x, w0[j], acc[r][j]);
                    acc[r][j] = fma2(xq.y, w1[j], acc[r][j]);
                }
            }
        }
        __syncthreads();
        buf ^= 1;
    }
    // epilogue: sum (even,odd) halves, store float4
#pragma unroll
    for (int r = 0; r < 4; r++) {
        int grow = rowBase + rg + 64 * r;
        if (grow < n) {
            float2 a0 = unpack2(acc[r][0]);
            float2 a1 = unpack2(acc[r][1]);
            float2 a2 = unpack2(acc[r][2]);
            float2 a3 = unpack2(acc[r][3]);
            reinterpret_cast<float4*>(&g_h1[(size_t)grow * HID])[jg] =
                make_float4(a0.x + a0.y, a1.x + a1.y, a2.x + a2.y, a3.x + a3.y);
        }
    }
}

// ---------------- CSR build ----------------
__global__ void k_zero_cnt(int n) {
    int i = blockIdx.x * blockDim.x + threadIdx.x;
    if (i < n) g_cnt[i] = 0;
}

__global__ void k_hist(const int* __restrict__ dst, int e) {
    int i = blockIdx.x * blockDim.x + threadIdx.x;
    if (i < e) atomicAdd(&g_cnt[dst[i]], 1);
}

__global__ void __launch_bounds__(256) k_scanA(int n) {
    __shared__ int s[256];
    int t = threadIdx.x;
    int i = blockIdx.x * 256 + t;
    int v = (i < n) ? g_cnt[i] : 0;
    s[t] = v;
    __syncthreads();
#pragma unroll
    for (int off = 1; off < 256; off <<= 1) {
        int add = (t >= off) ? s[t - off] : 0;
        __syncthreads();
        s[t] += add;
        __syncthreads();
    }
    if (i < n) g_pre[i] = s[t] - v;               // exclusive
    if (t == 255) g_bsum[blockIdx.x] = s[255];
}

__global__ void __launch_bounds__(512) k_scanB(int nb) {
    __shared__ int s[512];
    int t = threadIdx.x;
    int v = (t < nb) ? g_bsum[t] : 0;
    s[t] = v;
    __syncthreads();
#pragma unroll
    for (int off = 1; off < 512; off <<= 1) {
        int add = (t >= off) ? s[t - off] : 0;
        __syncthreads();
        s[t] += add;
        __syncthreads();
    }
    if (t < nb) g_boff[t] = s[t] - v;             // exclusive
}

__global__ void k_scanC(int n) {
    int i = blockIdx.x * blockDim.x + threadIdx.x;
    if (i >= n) return;
    int rp = g_pre[i] + g_boff[i >> 8];
    g_rowptr[i] = rp;
    g_cur[i] = rp;
    g_dinv[i] = rsqrtf((float)g_cnt[i] + 1.0f);   // +1 self loop
    if (i == n - 1) g_rowptr[n] = rp + g_cnt[i];
}

__global__ void k_scatter(const int* __restrict__ src,
                          const int* __restrict__ dst, int e) {
    int i = blockIdx.x * blockDim.x + threadIdx.x;
    if (i >= e) return;
    int s = src[i];
    int d = dst[i];
    float w = g_dinv[s] * g_dinv[d];
    int pos = atomicAdd(&g_cur[d], 1);
    g_csr[pos] = make_int2(s, __float_as_int(w));
}

// ---------------- gather layer 1 (fused self-loop + bias + relu) ----------------
__global__ void __launch_bounds__(256) k_gather1(const float* __restrict__ b1, int n) {
    int wid = (blockIdx.x * 256 + threadIdx.x) >> 5;
    if (wid >= n) return;
    int lane = threadIdx.x & 31;
    int ql = lane & 7, qh = lane >> 3;
    int row = g_rowptr[wid], end = g_rowptr[wid + 1];

    float2 acc = make_float2(0.f, 0.f);
    for (int i = row + qh; i < end; i += 4) {
        int2 ec = g_csr[i];
        float w = __int_as_float(ec.y);
        float2 hv = *reinterpret_cast<const float2*>(&g_h1[(size_t)ec.x * HID + ql * 2]);
        acc.x += w * hv.x;
        acc.y += w * hv.y;
    }
    acc.x += __shfl_xor_sync(0xffffffffu, acc.x, 8);
    acc.y += __shfl_xor_sync(0xffffffffu, acc.y, 8);
    acc.x += __shfl_xor_sync(0xffffffffu, acc.x, 16);
    acc.y += __shfl_xor_sync(0xffffffffu, acc.y, 16);

    float di = g_dinv[wid];
    float sl = di * di;
    float2 hv = *reinterpret_cast<const float2*>(&g_h1[(size_t)wid * HID + ql * 2]);
    float2 bb = *reinterpret_cast<const float2*>(&b1[ql * 2]);
    float2 r;
    r.x = fmaxf(acc.x + hv.x * sl + bb.x, 0.f);
    r.y = fmaxf(acc.y + hv.y * sl + bb.y, 0.f);
    if (qh == 0)
        *reinterpret_cast<float2*>(&g_hr[(size_t)wid * HID + ql * 2]) = r;
}

// ---------------- gather layer 2 (fused W2 GEMM + log-softmax) ----------------
__global__ void __launch_bounds__(256) k_gather2(const float* __restrict__ W2,
                                                 const float* __restrict__ b2,
                                                 float* __restrict__ out, int n) {
    __shared__ float W2s[HID * OUT_CH];  // 4 KB
    for (int i = threadIdx.x; i < HID * OUT_CH; i += 256) W2s[i] = W2[i];
    __syncthreads();

    int wid = (blockIdx.x * 256 + threadIdx.x) >> 5;
    if (wid >= n) return;
    int lane = threadIdx.x & 31;
    int ql = lane & 7, qh = lane >> 3;
    int row = g_rowptr[wid], end = g_rowptr[wid + 1];

    float2 acc = make_float2(0.f, 0.f);
    for (int i = row + qh; i < end; i += 4) {
        int2 ec = g_csr[i];
        float w = __int_as_float(ec.y);
        float2 hv = *reinterpret_cast<const float2*>(&g_hr[(size_t)ec.x * HID + ql * 2]);
        acc.x += w * hv.x;
        acc.y += w * hv.y;
    }
    acc.x += __shfl_xor_sync(0xffffffffu, acc.x, 8);
    acc.y += __shfl_xor_sync(0xffffffffu, acc.y, 8);
    acc.x += __shfl_xor_sync(0xffffffffu, acc.x, 16);
    acc.y += __shfl_xor_sync(0xffffffffu, acc.y, 16);

    float di = g_dinv[wid];
    float sl = di * di;
    float2 hv = *reinterpret_cast<const float2*>(&g_hr[(size_t)wid * HID + ql * 2]);
    float tx = acc.x + hv.x * sl;   // t[2*ql] (lanes 0..7 hold the 16-dim vector)
    float ty = acc.y + hv.y * sl;   // t[2*ql+1]

    float y0 = b2[lane];
    float y1 = b2[lane + 32];
#pragma unroll
    for (int k = 0; k < 8; k++) {
        float a = __shfl_sync(0xffffffffu, tx, k);
        float b = __shfl_sync(0xffffffffu, ty, k);
        y0 += a * W2s[(2 * k) * OUT_CH + lane]      + b * W2s[(2 * k + 1) * OUT_CH + lane];
        y1 += a * W2s[(2 * k) * OUT_CH + lane + 32] + b * W2s[(2 * k + 1) * OUT_CH + lane + 32];
    }
    float m = fmaxf(y0, y1);
#pragma unroll
    for (int o = 16; o; o >>= 1) m = fmaxf(m, __shfl_xor_sync(0xffffffffu, m, o));
    float se = expf(y0 - m) + expf(y1 - m);
#pragma unroll
    for (int o = 16; o; o >>= 1) se += __shfl_xor_sync(0xffffffffu, se, o);
    float lg = m + logf(se);
    out[(size_t)wid * OUT_CH + lane]      = y0 - lg;
    out[(size_t)wid * OUT_CH + lane + 32] = y1 - lg;
}

// ---------------- launch ----------------
extern "C" void kernel_launch(void* const* d_in, const int* in_sizes, int n_in,
                              void* d_out, int out_size) {
    const float* x    = (const float*)d_in[0];
    const int*   ei   = (const int*)d_in[1];     // int32 (JAX x64 disabled)
    const float* W1   = (const float*)d_in[2];
    const float* b1   = (const float*)d_in[3];
    const float* W2   = (const float*)d_in[4];
    const float* b2   = (const float*)d_in[5];
    float* out        = (float*)d_out;

    const int n = in_sizes[0] / IN_CH;       // 100000
    const int e = in_sizes[1] / 2;           // 3200000
    const int* src = ei;
    const int* dst = ei + e;

    const int TB = 256;
    int gb_n = (n + TB - 1) / TB;            // == NBLK
    int gb_e = (e + TB - 1) / TB;
    int gb_w = (n * 32 + TB - 1) / TB;       // warp-per-node kernels

    // gemm1 kept as launch #4 — ncu profiles the 4th launch.
    k_zero_cnt<<<gb_n, TB>>>(n);             // 1
    k_hist<<<gb_e, TB>>>(dst, e);            // 2
    k_scanA<<<gb_n, TB>>>(n);                // 3
    k_gemm1<<<gb_n, 256>>>(x, W1, n);        // 4  <-- profiled
    k_scanB<<<1, 512>>>(gb_n);               // 5
    k_scanC<<<gb_n, TB>>>(n);                // 6
    k_scatter<<<gb_e, TB>>>(src, dst, e);    // 7
    k_gather1<<<gb_w, TB>>>(b1, n);          // 8
    k_gather2<<<gb_w, TB>>>(W2, b2, out, n); // 9
}